// round 15
// baseline (speedup 1.0000x reference)
#include <cuda_runtime.h>
#include <cstdint>
#include <cstddef>

// Problem constants (fixed by the dataset)
#define E_DIM 128
#define S_DIM 64
#define P_DIM 256
#define B_DIM 4096
#define ROW_FLOATS (S_DIM * E_DIM)          // 8192 floats = 32 KB
#define ROW_BYTES  (ROW_FLOATS * 4)
#define N_STAGES   3
#define N_CWARPS   16                        // compute warps
#define N_CTHREADS (32 * N_CWARPS)           // 512 consumer threads
#define N_THREADS  (N_CTHREADS + 32)         // +1 producer warp = 544
#define SEGS_PER_WARP (S_DIM / N_CWARPS)     // 4
#define MAX_ROWS_PER_CTA 32                  // ceil(4096/152) + margin

// ---------------------------------------------------------------------------
// Path metadata lives in __constant__ memory: LDC goes through the constant
// cache (separate port), removing ~256 meta wavefronts/row from L1tex.
// meta.x = (i1*32)<<16 | (i2*32)  (float4-unit offsets), meta.y = bits(coeff)
// seg[s] = start of segment s in meta (sorted by i3); ord = segments ranked
// by descending path count (for snake load balancing).
// ---------------------------------------------------------------------------
struct PathConst {
    int2 meta[P_DIM];
    int  seg[S_DIM + 1];
    int  ord[S_DIM];
};
__constant__ PathConst c_pc;
__device__   PathConst d_pc_stage;           // written by prep, memcpy'd to c_pc

// ---------------------------------------------------------------------------
// Prep: deterministic stable counting-sort of 256 paths by i3 + segment rank.
// One block, 256 threads, ~2 us. Runs every replay (graph-safe, deterministic).
// ---------------------------------------------------------------------------
__global__ void prep_paths_kernel(const float* __restrict__ path_coeff,
                                  const int*   __restrict__ path_idx)
{
    __shared__ int s_i3[P_DIM];
    __shared__ int s_cnt[S_DIM + 1];

    const int t  = threadIdx.x;              // 0..255
    const int i1 = path_idx[t * 3 + 0];
    const int i2 = path_idx[t * 3 + 1];
    const int i3 = path_idx[t * 3 + 2];
    s_i3[t] = i3;
    if (t <= S_DIM) s_cnt[t] = 0;
    __syncthreads();

    atomicAdd(&s_cnt[i3 + 1], 1);
    __syncthreads();

    if (t == 0) {                            // inclusive prefix over 65 ints
        int acc = 0;
        #pragma unroll
        for (int i = 0; i <= S_DIM; i++) { acc += s_cnt[i]; s_cnt[i] = acc; }
    }
    __syncthreads();

    if (t <= S_DIM) d_pc_stage.seg[t] = s_cnt[t];

    // Stable rank within segment -> sorted position (same order as before:
    // identical accumulation order, bit-identical results).
    int rank = 0;
    for (int j = 0; j < t; j++) rank += (s_i3[j] == i3) ? 1 : 0;
    d_pc_stage.meta[s_cnt[i3] + rank] =
        make_int2(((i1 * (E_DIM / 4)) << 16) | (i2 * (E_DIM / 4)),
                  __float_as_int(path_coeff[t]));

    // Segment order by descending path count (index tiebreak), parallel rank.
    if (t < S_DIM) {
        const int myc = s_cnt[t + 1] - s_cnt[t];
        int rk = 0;
        #pragma unroll 4
        for (int j = 0; j < S_DIM; j++) {
            const int cj = s_cnt[j + 1] - s_cnt[j];
            rk += (cj > myc || (cj == myc && j < t)) ? 1 : 0;
        }
        d_pc_stage.ord[rk] = t;
    }
}

// ---------------------------------------------------------------------------
// Main kernel shared-memory layout (dynamic):
//   [0,24)    full mbarrier[3]   (tx-based, producer -> consumers)
//   [24,48)   empty mbarrier[3]  (16 arrivals, consumers -> producer)
//   [64,192)  s_ridx[32]         (this CTA's x_idx values, staged)
//   [4096 + st*65536) : stage st = [sx 32KB][sy 32KB]
// ---------------------------------------------------------------------------
#define OFF_FULL   0
#define OFF_EMPTY  24
#define OFF_RIDX   64
#define OFF_STAGE  4096
#define STAGE_BYTES (2 * ROW_BYTES)
#define SMEM_BYTES (OFF_STAGE + N_STAGES * STAGE_BYTES)   // 200704

__device__ __forceinline__ uint32_t smem_u32(const void* p) {
    uint32_t a;
    asm("{ .reg .u64 t; cvta.to.shared.u64 t, %1; cvt.u32.u64 %0, t; }"
        : "=r"(a) : "l"(p));
    return a;
}

__device__ __forceinline__ void mbar_wait(uint32_t mbar, uint32_t parity) {
    uint32_t done;
    asm volatile(
        "{\n\t"
        ".reg .pred p;\n\t"
        "mbarrier.try_wait.parity.acquire.cta.shared::cta.b64 p, [%1], %2;\n\t"
        "selp.b32 %0, 1, 0, p;\n\t"
        "}" : "=r"(done) : "r"(mbar), "r"(parity) : "memory");
    if (!done) {
        asm volatile(
            "{\n\t"
            ".reg .pred P1;\n\t"
            "W_%=:\n\t"
            "mbarrier.try_wait.parity.acquire.cta.shared::cta.b64 P1, [%0], %1, 0x989680;\n\t"
            "@P1 bra.uni D_%=;\n\t"
            "bra.uni W_%=;\n\t"
            "D_%=:\n\t"
            "}" :: "r"(mbar), "r"(parity) : "memory");
    }
}

__global__ __launch_bounds__(N_THREADS, 1)
void seg_poly_main(const float* __restrict__ x_table,
                   const float* __restrict__ y,
                   const int*   __restrict__ x_idx,
                   float*       __restrict__ out)
{
    extern __shared__ char smem[];
    int* s_ridx = (int*)(smem + OFF_RIDX);

    const int t    = threadIdx.x;            // 0..543
    const int warp = t >> 5;                 // 0..16 (16 = producer)
    const int lane = t & 31;
    const int G    = gridDim.x;
    const int r0   = blockIdx.x;

    const uint32_t full0  = smem_u32(smem + OFF_FULL);
    const uint32_t empty0 = smem_u32(smem + OFF_EMPTY);

    // --- minimal shared init, then ONE CTA-wide barrier --------------------
    if (t < N_STAGES) {
        asm volatile("mbarrier.init.shared.b64 [%0], 1;"
                     :: "r"(full0 + 8u * t) : "memory");
        asm volatile("mbarrier.init.shared.b64 [%0], %1;"
                     :: "r"(empty0 + 8u * t), "r"(N_CWARPS) : "memory");
    }
    if (t < MAX_ROWS_PER_CTA) {              // stage this CTA's x_idx values
        const int r = r0 + t * G;
        s_ridx[t] = (r < B_DIM) ? x_idx[r] : 0;
    }
    __syncthreads();                         // the ONLY CTA-wide barrier

    if (warp == N_CWARPS) {
        // ================== PRODUCER warp (lane 0 only) ====================
        if (lane == 0) {
            int k = 0;
            for (int r = r0; r < B_DIM; r += G, k++) {
                const int st = k % N_STAGES;
                const int u  = k / N_STAGES;
                if (u > 0)                       // stage reusable?
                    mbar_wait(empty0 + 8u * st, (u - 1) & 1);

                const uint32_t fb = full0 + 8u * st;
                asm volatile("mbarrier.arrive.expect_tx.shared.b64 _, [%0], %1;"
                             :: "r"(fb), "r"(STAGE_BYTES) : "memory");
                const uint32_t dst = smem_u32(smem + OFF_STAGE) + st * STAGE_BYTES;
                const char* xsrc = (const char*)
                    (x_table + (size_t)s_ridx[k] * ROW_FLOATS);
                const char* ysrc = (const char*)(y + (size_t)r * ROW_FLOATS);
                asm volatile(
                    "cp.async.bulk.shared::cta.global.mbarrier::complete_tx::bytes "
                    "[%0], [%1], %2, [%3];"
                    :: "r"(dst), "l"(xsrc), "r"(ROW_BYTES), "r"(fb) : "memory");
                asm volatile(
                    "cp.async.bulk.shared::cta.global.mbarrier::complete_tx::bytes "
                    "[%0], [%1], %2, [%3];"
                    :: "r"(dst + ROW_BYTES), "l"(ysrc), "r"(ROW_BYTES), "r"(fb) : "memory");
            }
        }
    } else {
        // ================== CONSUMER warps (0..15) =========================
        // Segment assignment straight from __constant__ (no smem, no barriers):
        // snake over rank order -> balanced load.
        int s3v[SEGS_PER_WARP], begs[SEGS_PER_WARP], ends[SEGS_PER_WARP];
        #pragma unroll
        for (int i = 0; i < SEGS_PER_WARP; i++) {
            const int pos = (i & 1) ? (N_CWARPS - 1 - warp) : warp;
            const int s3  = c_pc.ord[i * N_CWARPS + pos];
            s3v[i]  = s3;
            begs[i] = c_pc.seg[s3];
            ends[i] = c_pc.seg[s3 + 1];
        }

        int k = 0;
        for (int r = r0; r < B_DIM; r += G, k++) {
            const int st = k % N_STAGES;
            const int u  = k / N_STAGES;

            mbar_wait(full0 + 8u * st, u & 1);   // row data ready

            const float4* sx4 = (const float4*)(smem + OFF_STAGE + st * STAGE_BYTES);
            const float4* sy4 = sx4 + (ROW_FLOATS / 4);
            float4* o4 = (float4*)(out + (size_t)r * ROW_FLOATS);

            #pragma unroll
            for (int i = 0; i < SEGS_PER_WARP; i++) {
                const int s3  = s3v[i];
                const int beg = begs[i];
                const int end = ends[i];
                float4 acc = make_float4(0.f, 0.f, 0.f, 0.f);
                #pragma unroll 2
                for (int j = beg; j < end; j++) {
                    const int2  m  = c_pc.meta[j];      // LDC (const port!)
                    const float c  = __int_as_float(m.y);
                    const int   a1 = m.x >> 16;         // float4-unit offsets
                    const int   a2 = m.x & 0xFFFF;
                    const float4 xv = sx4[a1 + lane];   // LDS.128, conflict-free
                    const float4 yv = sy4[a2 + lane];
                    acc.x = fmaf(c * xv.x, yv.x, acc.x);
                    acc.y = fmaf(c * xv.y, yv.y, acc.y);
                    acc.z = fmaf(c * xv.z, yv.z, acc.z);
                    acc.w = fmaf(c * xv.w, yv.w, acc.w);
                }
                o4[s3 * (E_DIM / 4) + lane] = acc;      // STG.128, coalesced
            }

            // this warp is done reading stage st
            if (lane == 0) {
                asm volatile("mbarrier.arrive.shared.b64 _, [%0];"
                             :: "r"(empty0 + 8u * st) : "memory");
            }
        }
    }
}

// ---------------------------------------------------------------------------
// Launch wrapper. Inputs (metadata order):
//   0: x_table f32 [N,S*E]  1: y f32 [B,S*E]  2: path_coeff f32 [P]
//   3: x_idx i32 [B]        4: path_idx i32 [P,3]      out: f32 [B,S*E]
// Sequence (one stream, graph-capturable, allocation-free):
//   prep kernel -> async D2D memcpy into __constant__ -> main kernel
// ---------------------------------------------------------------------------
extern "C" void kernel_launch(void* const* d_in, const int* in_sizes, int n_in,
                              void* d_out, int out_size)
{
    const float* x_table    = (const float*)d_in[0];
    const float* y          = (const float*)d_in[1];
    const float* path_coeff = (const float*)d_in[2];
    const int*   x_idx      = (const int*)  d_in[3];
    const int*   path_idx   = (const int*)  d_in[4];
    float*       out        = (float*)d_out;

    (void)in_sizes; (void)n_in; (void)out_size;

    static int   sm_count = 0;
    static void* stage_addr = nullptr;
    if (sm_count == 0) {
        cudaDeviceGetAttribute(&sm_count, cudaDevAttrMultiProcessorCount, 0);
        if (sm_count <= 0) sm_count = 148;
        cudaFuncSetAttribute(seg_poly_main,
                             cudaFuncAttributeMaxDynamicSharedMemorySize,
                             SMEM_BYTES);
        cudaGetSymbolAddress(&stage_addr, d_pc_stage);
    }

    prep_paths_kernel<<<1, P_DIM>>>(path_coeff, path_idx);
    cudaMemcpyToSymbolAsync(c_pc, stage_addr, sizeof(PathConst), 0,
                            cudaMemcpyDeviceToDevice, 0);
    seg_poly_main<<<sm_count, N_THREADS, SMEM_BYTES>>>(x_table, y, x_idx, out);
}

// round 16
// speedup vs baseline: 1.1123x; 1.1123x over previous
#include <cuda_runtime.h>
#include <cstdint>
#include <cstddef>

// Problem constants (fixed by the dataset)
#define E_DIM 128
#define S_DIM 64
#define P_DIM 256
#define B_DIM 4096
#define ROW_FLOATS (S_DIM * E_DIM)          // 8192 floats = 32 KB
#define ROW_BYTES  (ROW_FLOATS * 4)
#define N_STAGES   3
#define N_CWARPS   16                        // compute warps
#define N_CTHREADS (32 * N_CWARPS)           // 512 consumer threads
#define N_THREADS  (N_CTHREADS + 32)         // +1 producer warp = 544
#define SEGS_PER_WARP (S_DIM / N_CWARPS)     // 4
#define MAX_ROWS_PER_CTA 32                  // ceil(4096/152) + margin

// ---------------------------------------------------------------------------
// Shared-memory layout (dynamic):
//   [0,24)       full mbarrier[3]   (tx-based, producer -> consumers)
//   [24,48)      empty mbarrier[3]  (16 arrivals, consumers -> producer)
//   [64,324)     seg_start[65]
//   [328,2376)   meta int2[256]     (sorted by i3)
//   [2376,3400)  prep scratch s_i3[256]
//   [3400,3660)  prep scratch s_cnt[65]
//   [3664,3792)  s_ridx[32]         (this CTA's x_idx values, staged)
//   [3792,4048)  s_order[64]        (segments ranked by path count, desc)
//   [4096 + st*65536) : stage st = [sx 32KB][sy 32KB]
// ---------------------------------------------------------------------------
#define OFF_FULL   0
#define OFF_EMPTY  24
#define OFF_SEG    64
#define OFF_META   328
#define OFF_I3     2376
#define OFF_CNT    3400
#define OFF_RIDX   3664
#define OFF_ORDER  3792
#define OFF_STAGE  4096
#define STAGE_BYTES (2 * ROW_BYTES)
#define SMEM_BYTES (OFF_STAGE + N_STAGES * STAGE_BYTES)   // 200704

__device__ __forceinline__ uint32_t smem_u32(const void* p) {
    uint32_t a;
    asm("{ .reg .u64 t; cvta.to.shared.u64 t, %1; cvt.u32.u64 %0, t; }"
        : "=r"(a) : "l"(p));
    return a;
}

__device__ __forceinline__ void mbar_wait(uint32_t mbar, uint32_t parity) {
    uint32_t done;
    asm volatile(
        "{\n\t"
        ".reg .pred p;\n\t"
        "mbarrier.try_wait.parity.acquire.cta.shared::cta.b64 p, [%1], %2;\n\t"
        "selp.b32 %0, 1, 0, p;\n\t"
        "}" : "=r"(done) : "r"(mbar), "r"(parity) : "memory");
    if (!done) {
        asm volatile(
            "{\n\t"
            ".reg .pred P1;\n\t"
            "W_%=:\n\t"
            "mbarrier.try_wait.parity.acquire.cta.shared::cta.b64 P1, [%0], %1, 0x989680;\n\t"
            "@P1 bra.uni D_%=;\n\t"
            "bra.uni W_%=;\n\t"
            "D_%=:\n\t"
            "}" :: "r"(mbar), "r"(parity) : "memory");
    }
}

// Consumer-only barrier (producer warp never participates).
__device__ __forceinline__ void consumer_bar() {
    asm volatile("bar.sync 1, %0;" :: "r"(N_CTHREADS) : "memory");
}

__global__ __launch_bounds__(N_THREADS, 1)
void seg_poly_main(const float* __restrict__ x_table,
                   const float* __restrict__ y,
                   const int*   __restrict__ x_idx,
                   const float* __restrict__ path_coeff,
                   const int*   __restrict__ path_idx,
                   float*       __restrict__ out)
{
    extern __shared__ char smem[];
    int*  sseg   = (int*) (smem + OFF_SEG);
    int2* smeta  = (int2*)(smem + OFF_META);
    int*  s_i3   = (int*) (smem + OFF_I3);
    int*  s_cnt  = (int*) (smem + OFF_CNT);
    int*  s_ridx = (int*) (smem + OFF_RIDX);
    int*  s_ord  = (int*) (smem + OFF_ORDER);

    const int t    = threadIdx.x;            // 0..543
    const int warp = t >> 5;                 // 0..16 (16 = producer)
    const int lane = t & 31;
    const int G    = gridDim.x;
    const int r0   = blockIdx.x;

    const uint32_t full0  = smem_u32(smem + OFF_FULL);
    const uint32_t empty0 = smem_u32(smem + OFF_EMPTY);

    // --- minimal shared init, then ONE CTA-wide barrier --------------------
    if (t < N_STAGES) {
        asm volatile("mbarrier.init.shared.b64 [%0], 1;"
                     :: "r"(full0 + 8u * t) : "memory");
        asm volatile("mbarrier.init.shared.b64 [%0], %1;"
                     :: "r"(empty0 + 8u * t), "r"(N_CWARPS) : "memory");
    }
    if (t <= S_DIM) s_cnt[t] = 0;
    if (t < MAX_ROWS_PER_CTA) {              // stage this CTA's x_idx values
        const int r = r0 + t * G;
        s_ridx[t] = (r < B_DIM) ? x_idx[r] : 0;
    }
    __syncthreads();                         // the ONLY CTA-wide barrier

    if (warp == N_CWARPS) {
        // ================== PRODUCER warp (lane 0 only) ====================
        // Starts copying immediately; prep runs concurrently on consumers.
        if (lane == 0) {
            int k = 0;
            for (int r = r0; r < B_DIM; r += G, k++) {
                const int st = k % N_STAGES;
                const int u  = k / N_STAGES;
                if (u > 0)                       // stage reusable?
                    mbar_wait(empty0 + 8u * st, (u - 1) & 1);

                const uint32_t fb = full0 + 8u * st;
                asm volatile("mbarrier.arrive.expect_tx.shared.b64 _, [%0], %1;"
                             :: "r"(fb), "r"(STAGE_BYTES) : "memory");
                const uint32_t dst = smem_u32(smem + OFF_STAGE) + st * STAGE_BYTES;
                const char* xsrc = (const char*)
                    (x_table + (size_t)s_ridx[k] * ROW_FLOATS);
                const char* ysrc = (const char*)(y + (size_t)r * ROW_FLOATS);
                asm volatile(
                    "cp.async.bulk.shared::cta.global.mbarrier::complete_tx::bytes "
                    "[%0], [%1], %2, [%3];"
                    :: "r"(dst), "l"(xsrc), "r"(ROW_BYTES), "r"(fb) : "memory");
                asm volatile(
                    "cp.async.bulk.shared::cta.global.mbarrier::complete_tx::bytes "
                    "[%0], [%1], %2, [%3];"
                    :: "r"(dst + ROW_BYTES), "l"(ysrc), "r"(ROW_BYTES), "r"(fb) : "memory");
            }
        }
    } else {
        // ================== CONSUMER warps (0..15) =========================
        // --- prep: stable counting-sort of 256 paths by i3 (consumer bars) -
        int i1 = 0, i2 = 0, i3 = 0;
        if (t < P_DIM) {
            i1 = path_idx[t * 3 + 0];
            i2 = path_idx[t * 3 + 1];
            i3 = path_idx[t * 3 + 2];
            s_i3[t] = i3;
        }
        consumer_bar();
        if (t < P_DIM) atomicAdd(&s_cnt[i3 + 1], 1);
        consumer_bar();
        if (t == 0) {
            int acc = 0;
            #pragma unroll
            for (int i = 0; i <= S_DIM; i++) { acc += s_cnt[i]; s_cnt[i] = acc; }
        }
        consumer_bar();
        if (t <= S_DIM) sseg[t] = s_cnt[t];
        if (t < P_DIM) {
            int rank = 0;                    // stable rank within segment
            for (int j = 0; j < t; j++) rank += (s_i3[j] == i3) ? 1 : 0;
            smeta[s_cnt[i3] + rank] =
                make_int2(((i1 * (E_DIM / 4)) << 16) | (i2 * (E_DIM / 4)),
                          __float_as_int(path_coeff[t]));
        }
        consumer_bar();

        // --- parallel rank: order segments by path count (desc, idx tiebrk)
        if (t < S_DIM) {
            const int myc = sseg[t + 1] - sseg[t];
            int rk = 0;
            #pragma unroll 4
            for (int j = 0; j < S_DIM; j++) {
                const int cj = sseg[j + 1] - sseg[j];   // broadcast LDS
                rk += (cj > myc || (cj == myc && j < t)) ? 1 : 0;
            }
            s_ord[rk] = t;
        }
        consumer_bar();

        // --- snake assignment + flat warp-local path list ------------------
        int s3v[SEGS_PER_WARP], begs[SEGS_PER_WARP];
        int pbeg[SEGS_PER_WARP], pend[SEGS_PER_WARP];
        int total = 0;
        #pragma unroll
        for (int i = 0; i < SEGS_PER_WARP; i++) {
            const int pos = (i & 1) ? (N_CWARPS - 1 - warp) : warp;
            const int s3  = s_ord[i * N_CWARPS + pos];
            s3v[i]  = s3;
            begs[i] = sseg[s3];
            pbeg[i] = total;
            total  += sseg[s3 + 1] - sseg[s3];
            pend[i] = total;
        }

        // Lane L caches the warp's L-th path meta in registers; the row loop
        // fetches meta via warp shuffle (SMSP-local) instead of LDS -> takes
        // ~256 meta wavefronts/row/SM off the L1 port.
        int meta_x = 0, meta_y = 0;
        {
            int base = 0;
            #pragma unroll
            for (int i = 0; i < SEGS_PER_WARP; i++) {
                const int len = pend[i] - pbeg[i];
                const int off = lane - base;
                if (off >= 0 && off < len) {
                    const int2 m = smeta[begs[i] + off];
                    meta_x = m.x; meta_y = m.y;
                }
                base += len;
            }
        }

        int k = 0;
        for (int r = r0; r < B_DIM; r += G, k++) {
            const int st = k % N_STAGES;
            const int u  = k / N_STAGES;

            mbar_wait(full0 + 8u * st, u & 1);   // row data ready

            const float4* sx4 = (const float4*)(smem + OFF_STAGE + st * STAGE_BYTES);
            const float4* sy4 = sx4 + (ROW_FLOATS / 4);
            float4* o4 = (float4*)(out + (size_t)r * ROW_FLOATS);

            #pragma unroll
            for (int i = 0; i < SEGS_PER_WARP; i++) {
                const int s3 = s3v[i];
                const int pb = pbeg[i];
                const int pe = pend[i];
                float4 acc = make_float4(0.f, 0.f, 0.f, 0.f);
                #pragma unroll 2
                for (int p = pb; p < pe; p++) {
                    int mx, my;
                    if (p < 32) {                       // shuffle (no L1 port)
                        mx = __shfl_sync(0xFFFFFFFFu, meta_x, p);
                        my = __shfl_sync(0xFFFFFFFFu, meta_y, p);
                    } else {                            // rare overflow path
                        const int2 m = smeta[begs[i] + (p - pb)];
                        mx = m.x; my = m.y;
                    }
                    const float c  = __int_as_float(my);
                    const int   a1 = mx >> 16;          // float4-unit offsets
                    const int   a2 = mx & 0xFFFF;
                    const float4 xv = sx4[a1 + lane];   // LDS.128, conflict-free
                    const float4 yv = sy4[a2 + lane];
                    acc.x = fmaf(c * xv.x, yv.x, acc.x);
                    acc.y = fmaf(c * xv.y, yv.y, acc.y);
                    acc.z = fmaf(c * xv.z, yv.z, acc.z);
                    acc.w = fmaf(c * xv.w, yv.w, acc.w);
                }
                o4[s3 * (E_DIM / 4) + lane] = acc;      // STG.128, coalesced
            }

            // this warp is done reading stage st
            if (lane == 0) {
                asm volatile("mbarrier.arrive.shared.b64 _, [%0];"
                             :: "r"(empty0 + 8u * st) : "memory");
            }
        }
    }
}

// ---------------------------------------------------------------------------
// Launch wrapper. Inputs (metadata order):
//   0: x_table f32 [N,S*E]  1: y f32 [B,S*E]  2: path_coeff f32 [P]
//   3: x_idx i32 [B]        4: path_idx i32 [P,3]      out: f32 [B,S*E]
// ---------------------------------------------------------------------------
extern "C" void kernel_launch(void* const* d_in, const int* in_sizes, int n_in,
                              void* d_out, int out_size)
{
    const float* x_table    = (const float*)d_in[0];
    const float* y          = (const float*)d_in[1];
    const float* path_coeff = (const float*)d_in[2];
    const int*   x_idx      = (const int*)  d_in[3];
    const int*   path_idx   = (const int*)  d_in[4];
    float*       out        = (float*)d_out;

    (void)in_sizes; (void)n_in; (void)out_size;

    static int sm_count = 0;
    if (sm_count == 0) {
        cudaDeviceGetAttribute(&sm_count, cudaDevAttrMultiProcessorCount, 0);
        if (sm_count <= 0) sm_count = 148;
        cudaFuncSetAttribute(seg_poly_main,
                             cudaFuncAttributeMaxDynamicSharedMemorySize,
                             SMEM_BYTES);
    }

    seg_poly_main<<<sm_count, N_THREADS, SMEM_BYTES>>>(
        x_table, y, x_idx, path_coeff, path_idx, out);
}